// round 6
// baseline (speedup 1.0000x reference)
#include <cuda_runtime.h>

// Problem constants (from reference): B=32, T=168, M=1024, A=8, H=64, O=1
#define Mu   1024
#define Au   8
#define Hu   64
#define PRE_BLOCKS 128   // blocks 0..127 produce the coefficient table (8 m/block)

// Coefficient tables (SoA, coalesced):
//   g_u0[m] = (u0,u1,u2,u3), g_u1[m] = (u4,u5,u6,u7)
//   g_c [m] = (c_mn, c_mx, c_const, 0)
// u[a] = sum_h assoc_w[m,a,h]*dense_w[m,h];  v = sum_h assoc_b[m,h]*dense_w[m,h]
// s = sum_h dense_w[m,h];  U = sum_a u[a]
// c_mn = s - U - v ; c_mx = v ; c_const = dense_b[m]
// out = dot(xt,u) + mn*c_mn + mx*c_mx + c_const   (LSTM state is dead code;
// the /(mx-mn) and *(mx-mn) cancel algebraically).
__device__ float4 g_u0[Mu];
__device__ float4 g_u1[Mu];
__device__ float4 g_c [Mu];
__device__ unsigned int g_ready;   // producer blocks completed (0..PRE_BLOCKS)
__device__ unsigned int g_done;    // blocks fully finished (for counter reset)

__device__ __forceinline__ float warp_sum(float v) {
    #pragma unroll
    for (int off = 16; off > 0; off >>= 1)
        v += __shfl_xor_sync(0xffffffffu, v, off);
    return v;
}

// Single self-synchronizing kernel.
//  * every block prefetches its streaming x data first (overlaps the wait)
//  * blocks 0..127 then compute 8 coefficients each and bump g_ready
//  * one warp per block spins on g_ready; others park at __syncthreads
//  * last block to finish resets the counters (graph-replay safe)
// launch_bounds(256,8) caps regs at 32 so the cold precompute path cannot
// depress occupancy of the streaming grid (spills land on 128 blocks only).
__global__ void __launch_bounds__(256, 8)
fused_kernel(const float* __restrict__ x,         // [B,T,M,A] contiguous
             float* __restrict__ out,             // [B,T,M]
             const float* __restrict__ assoc_w,   // [M,A,H]
             const float* __restrict__ assoc_b,   // [M,H]
             const float* __restrict__ dense_w,   // [M,H]
             const float* __restrict__ dense_b) { // [M]
    const int idx = blockIdx.x * blockDim.x + threadIdx.x;
    const int m   = ((blockIdx.x << 8) & (Mu - 1)) + threadIdx.x;

    // Streaming prefetch (no dependence on the coefficient table).
    const float4* xp = reinterpret_cast<const float4*>(x) + (size_t)idx * 2;
    const float4 a = __ldcs(xp);
    const float4 b = __ldcs(xp + 1);

    // ---- producer path: first 128 blocks build the coefficient table ----
    if (blockIdx.x < PRE_BLOCKS) {
        const int warp = threadIdx.x >> 5;
        const int lane = threadIdx.x & 31;
        const int mp = blockIdx.x * 8 + warp;          // one m per warp

        const float2 d  = reinterpret_cast<const float2*>(dense_w + mp * Hu)[lane];
        const float2 ab = reinterpret_cast<const float2*>(assoc_b + mp * Hu)[lane];

        float vals[10];
        #pragma unroll
        for (int aa = 0; aa < Au; aa++) {
            const float2 w = reinterpret_cast<const float2*>(
                assoc_w + ((size_t)mp * Au + aa) * Hu)[lane];
            vals[aa] = w.x * d.x + w.y * d.y;
        }
        vals[8] = ab.x * d.x + ab.y * d.y;   // v partial
        vals[9] = d.x + d.y;                 // s partial

        #pragma unroll
        for (int i = 0; i < 10; i++)
            vals[i] = warp_sum(vals[i]);

        if (lane == 0) {
            float U = vals[0] + vals[1] + vals[2] + vals[3]
                    + vals[4] + vals[5] + vals[6] + vals[7];
            g_u0[mp] = make_float4(vals[0], vals[1], vals[2], vals[3]);
            g_u1[mp] = make_float4(vals[4], vals[5], vals[6], vals[7]);
            g_c [mp] = make_float4(vals[9] - U - vals[8], vals[8],
                                   dense_b[mp], 0.0f);
        }
        __syncthreads();                       // all 8 warps' stores issued
        if (threadIdx.x == 0) {
            __threadfence();                   // release coefficient stores
            atomicAdd(&g_ready, 1u);
        }
    }

    // ---- wait for the full table (one polling warp per block) ----
    if (threadIdx.x == 0) {
        while (*(volatile unsigned int*)&g_ready < PRE_BLOCKS) { }
        __threadfence();                       // acquire
    }
    __syncthreads();

    // ---- streaming compute ----
    const float4 u0 = g_u0[m];                 // coalesced (consecutive float4)
    const float4 u1 = g_u1[m];
    const float4 c  = g_c [m];

    float mn = fminf(fminf(fminf(a.x, a.y), fminf(a.z, a.w)),
                     fminf(fminf(b.x, b.y), fminf(b.z, b.w)));
    float mx = fmaxf(fmaxf(fmaxf(a.x, a.y), fmaxf(a.z, a.w)),
                     fmaxf(fmaxf(b.x, b.y), fmaxf(b.z, b.w)));

    float dot = a.x * u0.x + a.y * u0.y + a.z * u0.z + a.w * u0.w
              + b.x * u1.x + b.y * u1.y + b.z * u1.z + b.w * u1.w;

    __stcs(out + idx, dot + mn * c.x + mx * c.y + c.z);

    // ---- counter reset so the captured graph replays identically ----
    __syncthreads();                           // whole block done
    if (threadIdx.x == 0) {
        unsigned int old = atomicAdd(&g_done, 1u);
        if (old == gridDim.x - 1) {            // last block in the grid
            g_ready = 0;
            g_done  = 0;
            __threadfence();
        }
    }
}

extern "C" void kernel_launch(void* const* d_in, const int* in_sizes, int n_in,
                              void* d_out, int out_size) {
    // metadata order: input, assoc_w, assoc_b, w_ih, w_hh, b_ih, b_hh, dense_w, dense_b
    const float* x        = (const float*)d_in[0];
    const float* assoc_w  = (const float*)d_in[1];
    const float* assoc_b  = (const float*)d_in[2];
    const float* dense_w  = (const float*)d_in[7];
    const float* dense_b  = (const float*)d_in[8];
    float* out            = (float*)d_out;

    const int n = out_size;                 // B*T*M = 5,505,024 = 21504 * 256
    const int threads = 256;
    const int blocks = n / threads;         // 21504

    fused_kernel<<<blocks, threads>>>(x, out, assoc_w, assoc_b, dense_w, dense_b);
}

// round 7
// speedup vs baseline: 1.3490x; 1.3490x over previous
#include <cuda_runtime.h>

// Problem constants (from reference): B=32, T=168, M=1024, A=8, H=64, O=1
#define Mu   1024
#define Au   8
#define Hu   64

// Persistent fused grid: 912 blocks x 256 threads.
// STRIDE = 912*256 = 233472 = 228*1024 -> multiple of M, so each thread's
// map-unit m is invariant across loop iterations (coefs live in registers).
#define FBLOCKS 912
#define FTHREADS 256

// Coefficient table (AoS): per map-unit m
//   [m*3+0] = (u0,u1,u2,u3) ; [m*3+1] = (u4,u5,u6,u7)
//   [m*3+2] = (c_mn, c_mx, c_const, 0)
// u[a] = sum_h assoc_w[m,a,h]*dense_w[m,h];  v = sum_h assoc_b[m,h]*dense_w[m,h]
// s = sum_h dense_w[m,h];  U = sum_a u[a]
// c_mn = s - U - v ; c_mx = v ; c_const = dense_b[m]
// out = dot(xt,u) + mn*c_mn + mx*c_mx + c_const   (LSTM state is dead code;
// the /(mx-mn) and *(mx-mn) cancel algebraically).
__device__ float4 g_coef[Mu * 3];

__device__ __forceinline__ float warp_sum(float v) {
    #pragma unroll
    for (int off = 16; off > 0; off >>= 1)
        v += __shfl_xor_sync(0xffffffffu, v, off);
    return v;
}

// One warp per map-unit m; 8 warps/block -> 128 blocks; full-ILP reductions.
// PDL trigger after the coefficient stores.
__global__ void __launch_bounds__(256)
precompute_kernel(const float* __restrict__ assoc_w,   // [M,A,H]
                  const float* __restrict__ assoc_b,   // [M,H]
                  const float* __restrict__ dense_w,   // [M,H]
                  const float* __restrict__ dense_b) { // [M]
    const int warp = threadIdx.x >> 5;
    const int lane = threadIdx.x & 31;
    const int m = blockIdx.x * 8 + warp;   // grid = 128

    const float2 d  = reinterpret_cast<const float2*>(dense_w + m * Hu)[lane];
    const float2 ab = reinterpret_cast<const float2*>(assoc_b + m * Hu)[lane];

    float vals[10];
    #pragma unroll
    for (int a = 0; a < Au; a++) {
        const float2 w = reinterpret_cast<const float2*>(
            assoc_w + ((size_t)m * Au + a) * Hu)[lane];
        vals[a] = w.x * d.x + w.y * d.y;
    }
    vals[8] = ab.x * d.x + ab.y * d.y;   // v partial
    vals[9] = d.x + d.y;                 // s partial

    #pragma unroll
    for (int i = 0; i < 10; i++)
        vals[i] = warp_sum(vals[i]);

    if (lane == 0) {
        float U = vals[0] + vals[1] + vals[2] + vals[3]
                + vals[4] + vals[5] + vals[6] + vals[7];
        g_coef[m * 3 + 0] = make_float4(vals[0], vals[1], vals[2], vals[3]);
        g_coef[m * 3 + 1] = make_float4(vals[4], vals[5], vals[6], vals[7]);
        g_coef[m * 3 + 2] = make_float4(vals[9] - U - vals[8], vals[8],
                                        dense_b[m], 0.0f);
    }

    cudaTriggerProgrammaticLaunchCompletion();
}

// Persistent grid-stride streaming kernel (PDL secondary).
//  * first x loads issued BEFORE the grid dependency wait (overlap)
//  * m invariant per thread -> coefficients loaded once into registers
//  * loop body: 2x LDG.128 (streaming) -> FMA/min/max -> 1x STG (streaming)
__global__ void __launch_bounds__(FTHREADS, 6)
fused_kernel(const float* __restrict__ x,   // [B,T,M,A] contiguous
             float* __restrict__ out,       // [B,T,M]
             int n) {                       // n = B*T*M
    const int idx0 = blockIdx.x * FTHREADS + threadIdx.x;
    const int stride = FBLOCKS * FTHREADS;          // 233472 = 228*1024
    const int m = idx0 & (Mu - 1);                  // invariant across iters

    // Prefetch iteration 0 before waiting on the coefficient producer.
    int i = idx0;
    const float4* xp = reinterpret_cast<const float4*>(x) + (size_t)i * 2;
    float4 a = __ldcs(xp);
    float4 b = __ldcs(xp + 1);

    cudaGridDependencySynchronize();                // g_coef now valid

    const float4 u0 = g_coef[m * 3 + 0];            // register-resident
    const float4 u1 = g_coef[m * 3 + 1];
    const float4 c  = g_coef[m * 3 + 2];

    while (i < n) {
        float mn = fminf(fminf(fminf(a.x, a.y), fminf(a.z, a.w)),
                         fminf(fminf(b.x, b.y), fminf(b.z, b.w)));
        float mx = fmaxf(fmaxf(fmaxf(a.x, a.y), fmaxf(a.z, a.w)),
                         fmaxf(fmaxf(b.x, b.y), fmaxf(b.z, b.w)));
        float dot = a.x * u0.x + a.y * u0.y + a.z * u0.z + a.w * u0.w
                  + b.x * u1.x + b.y * u1.y + b.z * u1.z + b.w * u1.w;
        float r = dot + mn * c.x + mx * c.y + c.z;

        int nexti = i + stride;
        if (nexti < n) {                            // prefetch next iteration
            const float4* np = reinterpret_cast<const float4*>(x)
                             + (size_t)nexti * 2;
            a = __ldcs(np);
            b = __ldcs(np + 1);
        }

        __stcs(out + i, r);
        i = nexti;
    }
}

extern "C" void kernel_launch(void* const* d_in, const int* in_sizes, int n_in,
                              void* d_out, int out_size) {
    // metadata order: input, assoc_w, assoc_b, w_ih, w_hh, b_ih, b_hh, dense_w, dense_b
    const float* x        = (const float*)d_in[0];
    const float* assoc_w  = (const float*)d_in[1];
    const float* assoc_b  = (const float*)d_in[2];
    const float* dense_w  = (const float*)d_in[7];
    const float* dense_b  = (const float*)d_in[8];
    float* out            = (float*)d_out;

    precompute_kernel<<<Mu / 8, 256>>>(assoc_w, assoc_b, dense_w, dense_b);

    const int n = out_size;                 // B*T*M = 5,505,024

    // PDL: fused may begin launching before precompute completes; the
    // device-side cudaGridDependencySynchronize() orders the coef reads.
    cudaLaunchConfig_t cfg = {};
    cfg.gridDim  = dim3(FBLOCKS, 1, 1);
    cfg.blockDim = dim3(FTHREADS, 1, 1);
    cfg.dynamicSmemBytes = 0;
    cfg.stream = 0;
    cudaLaunchAttribute attr[1];
    attr[0].id = cudaLaunchAttributeProgrammaticStreamSerialization;
    attr[0].val.programmaticStreamSerializationAllowed = 1;
    cfg.attrs = attr;
    cfg.numAttrs = 1;
    cudaLaunchKernelEx(&cfg, fused_kernel, x, out, n);
}

// round 8
// speedup vs baseline: 1.5015x; 1.1130x over previous
#include <cuda_runtime.h>

// Problem constants (from reference): B=32, T=168, M=1024, A=8, H=64, O=1
#define Mu   1024
#define Au   8
#define Hu   64

// Coefficient table (AoS): per map-unit m
//   [m*3+0] = (u0,u1,u2,u3) ; [m*3+1] = (u4,u5,u6,u7)
//   [m*3+2] = (c_mn, c_mx, c_const, 0)
// u[a] = sum_h assoc_w[m,a,h]*dense_w[m,h];  v = sum_h assoc_b[m,h]*dense_w[m,h]
// s = sum_h dense_w[m,h];  U = sum_a u[a]
// c_mn = s - U - v ; c_mx = v ; c_const = dense_b[m]
// out = dot(xt,u) + mn*c_mn + mx*c_mx + c_const   (LSTM state is dead code;
// the /(mx-mn) and *(mx-mn) cancel algebraically).
__device__ float4 g_coef[Mu * 3];

__device__ __forceinline__ float warp_sum(float v) {
    #pragma unroll
    for (int off = 16; off > 0; off >>= 1)
        v += __shfl_xor_sync(0xffffffffu, v, off);
    return v;
}

// One warp per map-unit m; 8 warps/block -> 128 blocks; full-ILP reductions.
// PDL trigger after the coefficient stores.
__global__ void __launch_bounds__(256)
precompute_kernel(const float* __restrict__ assoc_w,   // [M,A,H]
                  const float* __restrict__ assoc_b,   // [M,H]
                  const float* __restrict__ dense_w,   // [M,H]
                  const float* __restrict__ dense_b) { // [M]
    const int warp = threadIdx.x >> 5;
    const int lane = threadIdx.x & 31;
    const int m = blockIdx.x * 8 + warp;   // grid = 128

    const float2 d  = reinterpret_cast<const float2*>(dense_w + m * Hu)[lane];
    const float2 ab = reinterpret_cast<const float2*>(assoc_b + m * Hu)[lane];

    float vals[10];
    #pragma unroll
    for (int a = 0; a < Au; a++) {
        const float2 w = reinterpret_cast<const float2*>(
            assoc_w + ((size_t)m * Au + a) * Hu)[lane];
        vals[a] = w.x * d.x + w.y * d.y;
    }
    vals[8] = ab.x * d.x + ab.y * d.y;   // v partial
    vals[9] = d.x + d.y;                 // s partial

    #pragma unroll
    for (int i = 0; i < 10; i++)
        vals[i] = warp_sum(vals[i]);

    if (lane == 0) {
        float U = vals[0] + vals[1] + vals[2] + vals[3]
                + vals[4] + vals[5] + vals[6] + vals[7];
        g_coef[m * 3 + 0] = make_float4(vals[0], vals[1], vals[2], vals[3]);
        g_coef[m * 3 + 1] = make_float4(vals[4], vals[5], vals[6], vals[7]);
        g_coef[m * 3 + 2] = make_float4(vals[9] - U - vals[8], vals[8],
                                        dense_b[m], 0.0f);
    }

    cudaTriggerProgrammaticLaunchCompletion();
}

// ~ one occupancy wave: 148 SMs x 6 resident blocks (regs=30 @ 256 thr)
#define WAVE_BLOCKS 888
#define WAVE_ELEMS  (WAVE_BLOCKS * 256)

// Flat 1-elem/thread streaming kernel (empirically optimal shape, R3/R4).
// PDL secondary: issue this thread's 2 streaming loads PLUS L2 prefetches
// for the blocks 1 and 2 waves ahead, THEN wait on the producer — so DRAM
// stays busy during the PDL wait window instead of idling.
// n = 5,505,024 is an exact multiple of 256 -> no bounds check on idx.
__global__ void __launch_bounds__(256)
fused_kernel(const float* __restrict__ x,   // [B,T,M,A] contiguous
             float* __restrict__ out,       // [B,T,M]
             int n) {                       // n = B*T*M
    const int idx = blockIdx.x * blockDim.x + threadIdx.x;
    const int m   = idx & (Mu - 1);         // M = 1024, fastest dim

    const float4* xp = reinterpret_cast<const float4*>(x) + (size_t)idx * 2;
    const float4 a = __ldcs(xp);            // issued before the dependency wait
    const float4 b = __ldcs(xp + 1);

    // L2 prefetch for future waves (keeps DRAM busy during the PDL wait;
    // steady-state consumers of these lines hit L2 — no extra DRAM bytes).
    const int pf1 = idx + WAVE_ELEMS;
    const int pf2 = idx + 2 * WAVE_ELEMS;
    if (pf1 < n) {
        const float4* p1 = reinterpret_cast<const float4*>(x) + (size_t)pf1 * 2;
        asm volatile("prefetch.global.L2 [%0];" :: "l"(p1));
    }
    if (pf2 < n) {
        const float4* p2 = reinterpret_cast<const float4*>(x) + (size_t)pf2 * 2;
        asm volatile("prefetch.global.L2 [%0];" :: "l"(p2));
    }

    cudaGridDependencySynchronize();        // g_coef now valid

    const float4 u0 = g_coef[m * 3 + 0];
    const float4 u1 = g_coef[m * 3 + 1];
    const float4 c  = g_coef[m * 3 + 2];

    float mn = fminf(fminf(fminf(a.x, a.y), fminf(a.z, a.w)),
                     fminf(fminf(b.x, b.y), fminf(b.z, b.w)));
    float mx = fmaxf(fmaxf(fmaxf(a.x, a.y), fmaxf(a.z, a.w)),
                     fmaxf(fmaxf(b.x, b.y), fmaxf(b.z, b.w)));

    float dot = a.x * u0.x + a.y * u0.y + a.z * u0.z + a.w * u0.w
              + b.x * u1.x + b.y * u1.y + b.z * u1.z + b.w * u1.w;

    __stcs(out + idx, dot + mn * c.x + mx * c.y + c.z);
}

extern "C" void kernel_launch(void* const* d_in, const int* in_sizes, int n_in,
                              void* d_out, int out_size) {
    // metadata order: input, assoc_w, assoc_b, w_ih, w_hh, b_ih, b_hh, dense_w, dense_b
    const float* x        = (const float*)d_in[0];
    const float* assoc_w  = (const float*)d_in[1];
    const float* assoc_b  = (const float*)d_in[2];
    const float* dense_w  = (const float*)d_in[7];
    const float* dense_b  = (const float*)d_in[8];
    float* out            = (float*)d_out;

    precompute_kernel<<<Mu / 8, 256>>>(assoc_w, assoc_b, dense_w, dense_b);

    const int n = out_size;                 // B*T*M = 5,505,024 = 21504 * 256
    const int threads = 256;
    const int blocks = n / threads;         // 21504

    // PDL: fused may begin launching before precompute completes; the
    // device-side cudaGridDependencySynchronize() orders the coef reads.
    cudaLaunchConfig_t cfg = {};
    cfg.gridDim  = dim3(blocks, 1, 1);
    cfg.blockDim = dim3(threads, 1, 1);
    cfg.dynamicSmemBytes = 0;
    cfg.stream = 0;
    cudaLaunchAttribute attr[1];
    attr[0].id = cudaLaunchAttributeProgrammaticStreamSerialization;
    attr[0].val.programmaticStreamSerializationAllowed = 1;
    cfg.attrs = attr;
    cfg.numAttrs = 1;
    cudaLaunchKernelEx(&cfg, fused_kernel, x, out, n);
}